// round 10
// baseline (speedup 1.0000x reference)
#include <cuda_runtime.h>

#define NL   4
#define SEQ  34
#define DM   6
#define VOC  14
#define BPB  32
#define NTH  544                  /* 17 warps: warp w owns t0=w for 32 batches */
#define HROW 8                    /* 6 floats h-pairs + 2 pad: 32B row */
#define KVSTRIDE (SEQ*HROW + 4)   /* 276 floats */
#define KVBUF (BPB*KVSTRIDE)      /* 8832 floats per buffer */

#define FMA2(d,a,b,c) asm("fma.rn.f32x2 %0, %1, %2, %3;" : "=l"(d) : "l"(a), "l"(b), "l"(c))
#define MUL2(d,a,b)   asm("mul.rn.f32x2 %0, %1, %2;"     : "=l"(d) : "l"(a), "l"(b))
#define ADD2(d,a,b)   asm("add.rn.f32x2 %0, %1, %2;"     : "=l"(d) : "l"(a), "l"(b))

__device__ __forceinline__ unsigned long long pack2(float lo, float hi) {
    unsigned long long r;
    asm("mov.b64 %0, {%1, %2};" : "=l"(r) : "f"(lo), "f"(hi));
    return r;
}
__device__ __forceinline__ void unpack2(unsigned long long v, float& lo, float& hi) {
    asm("mov.b64 {%0, %1}, %2;" : "=f"(lo), "=f"(hi) : "l"(v));
}
__device__ __forceinline__ float ex2f(float x) {
    float r; asm("ex2.approx.f32 %0, %1;" : "=f"(r) : "f"(x)); return r;
}

__global__ __launch_bounds__(NTH, 2)   /* <=60 regs; x-state lives in smem now */
void addtx_kernel(const int*   __restrict__ g_idx,
                  const float* __restrict__ g_tok,
                  const float* __restrict__ g_pos,
                  const float* __restrict__ g_lnw,
                  const float* __restrict__ g_lnb,
                  const float* __restrict__ g_q1,
                  const float* __restrict__ g_k1,
                  const float* __restrict__ g_v1,
                  const float* __restrict__ g_q2,
                  const float* __restrict__ g_k2,
                  const float* __restrict__ g_v2,
                  const float* __restrict__ g_ow,
                  const float* __restrict__ g_lnfw,
                  const float* __restrict__ g_lnfb,
                  const float* __restrict__ g_hw,
                  float* __restrict__ g_out)
{
    __shared__ float sQ1[NL*9], sK1[NL*9], sV1[NL*9];
    __shared__ float sQ2[NL*9], sK2[NL*9], sV2[NL*9];
    __shared__ float sOW[NL*36];
    __shared__ float sLNW[NL*DM], sLNB[NL*DM];
    __shared__ float sLNF[2*DM];
    __shared__ float sHW[VOC*DM];
    __shared__ float sTOK[VOC*3];
    __shared__ float sPOS[SEQ*3];
    __shared__ float sX[2*DM][NTH];               // per-thread residual state (xA, xB)
    extern __shared__ __align__(16) float sKV[];   // [2][KVBUF] double buffer

    const int tid = threadIdx.x;

    for (int i = tid; i < NL*9; i += NTH) {
        sQ1[i]=g_q1[i]; sK1[i]=g_k1[i]; sV1[i]=g_v1[i];
        sQ2[i]=g_q2[i]; sK2[i]=g_k2[i]; sV2[i]=g_v2[i];
    }
    for (int i = tid; i < NL*36; i += NTH) sOW[i]=g_ow[i];
    for (int i = tid; i < NL*DM; i += NTH) { sLNW[i]=g_lnw[i]; sLNB[i]=g_lnb[i]; }
    if (tid < DM) { sLNF[tid]=g_lnfw[tid]; sLNF[DM+tid]=g_lnfb[tid]; }
    for (int i = tid; i < VOC*DM; i += NTH) sHW[i]=g_hw[i];
    for (int i = tid; i < VOC*3; i += NTH) sTOK[i]=g_tok[i];
    for (int i = tid; i < SEQ*3; i += NTH) sPOS[i]=g_pos[i];

    const int t0 = tid >> 5;            // warp id = first query position (0..16)
    const int bl = tid & 31;            // lane = batch within block
    const int b  = blockIdx.x * BPB + bl;
    const int tA = t0, tB = t0 + 17;

    __syncthreads();

    {   // initial embeddings -> smem x-state (own slot, no sync needed)
        const int tokA = g_idx[b*SEQ + tA];
        const int tokB = g_idx[b*SEQ + tB];
        #pragma unroll
        for (int d = 0; d < 3; d++) {
            sX[d][tid]      = sTOK[tokA*3+d];
            sX[3+d][tid]    = sPOS[tA*3+d];
            sX[6+d][tid]    = sTOK[tokB*3+d];
            sX[9+d][tid]    = sPOS[tB*3+d];
        }
    }

    const int kvoff = bl*KVSTRIDE;
    const float QS = 0.5773502691896258f * 1.4426950408889634f;  // 1/sqrt(3)*log2(e)

    #pragma unroll 1
    for (int l = 0; l < NL; l++) {
        float* kvb = sKV + (l & 1)*KVBUF + kvoff;
        const float* lw = &sLNW[l*DM];
        const float* lb = &sLNB[l*DM];

        // ---- layernorm both queries (x read from smem, h short-lived) ----
        unsigned long long uA0,uA1,uA2, uB0,uB1,uB2;
        {
            float h[DM];
            {
                float x0=sX[0][tid],x1=sX[1][tid],x2=sX[2][tid],
                      x3=sX[3][tid],x4=sX[4][tid],x5=sX[5][tid];
                float m = (x0+x1+x2+x3+x4+x5) * (1.0f/6.0f);
                h[0]=x0-m; h[1]=x1-m; h[2]=x2-m; h[3]=x3-m; h[4]=x4-m; h[5]=x5-m;
                float v = h[0]*h[0]+h[1]*h[1]+h[2]*h[2]+h[3]*h[3]+h[4]*h[4]+h[5]*h[5];
                float r = rsqrtf(v*(1.0f/6.0f) + 1e-5f);
                #pragma unroll
                for (int d=0; d<DM; d++) h[d] = h[d]*r*lw[d] + lb[d];
            }
            float4* dA = reinterpret_cast<float4*>(kvb + tA*HROW);
            dA[0] = make_float4(h[0],h[3],h[1],h[4]);
            *reinterpret_cast<float2*>(kvb + tA*HROW + 4) = make_float2(h[2],h[5]);
            float q1[3], q2[3];
            #pragma unroll
            for (int d=0; d<3; d++) {
                const float* ww;
                ww = &sQ1[l*9+d*3]; q1[d] = (ww[0]*h[0]+ww[1]*h[1]+ww[2]*h[2]) * QS;
                ww = &sQ2[l*9+d*3]; q2[d] = (ww[0]*h[3]+ww[1]*h[4]+ww[2]*h[5]) * QS;
            }
            uA0 = pack2(sK1[l*9+0]*q1[0]+sK1[l*9+3]*q1[1]+sK1[l*9+6]*q1[2],
                        sK2[l*9+0]*q2[0]+sK2[l*9+3]*q2[1]+sK2[l*9+6]*q2[2]);
            uA1 = pack2(sK1[l*9+1]*q1[0]+sK1[l*9+4]*q1[1]+sK1[l*9+7]*q1[2],
                        sK2[l*9+1]*q2[0]+sK2[l*9+4]*q2[1]+sK2[l*9+7]*q2[2]);
            uA2 = pack2(sK1[l*9+2]*q1[0]+sK1[l*9+5]*q1[1]+sK1[l*9+8]*q1[2],
                        sK2[l*9+2]*q2[0]+sK2[l*9+5]*q2[1]+sK2[l*9+8]*q2[2]);
        }
        {
            float h[DM];
            {
                float x0=sX[6][tid],x1=sX[7][tid],x2=sX[8][tid],
                      x3=sX[9][tid],x4=sX[10][tid],x5=sX[11][tid];
                float m = (x0+x1+x2+x3+x4+x5) * (1.0f/6.0f);
                h[0]=x0-m; h[1]=x1-m; h[2]=x2-m; h[3]=x3-m; h[4]=x4-m; h[5]=x5-m;
                float v = h[0]*h[0]+h[1]*h[1]+h[2]*h[2]+h[3]*h[3]+h[4]*h[4]+h[5]*h[5];
                float r = rsqrtf(v*(1.0f/6.0f) + 1e-5f);
                #pragma unroll
                for (int d=0; d<DM; d++) h[d] = h[d]*r*lw[d] + lb[d];
            }
            float4* dB = reinterpret_cast<float4*>(kvb + tB*HROW);
            dB[0] = make_float4(h[0],h[3],h[1],h[4]);
            *reinterpret_cast<float2*>(kvb + tB*HROW + 4) = make_float2(h[2],h[5]);
            float q1[3], q2[3];
            #pragma unroll
            for (int d=0; d<3; d++) {
                const float* ww;
                ww = &sQ1[l*9+d*3]; q1[d] = (ww[0]*h[0]+ww[1]*h[1]+ww[2]*h[2]) * QS;
                ww = &sQ2[l*9+d*3]; q2[d] = (ww[0]*h[3]+ww[1]*h[4]+ww[2]*h[5]) * QS;
            }
            uB0 = pack2(sK1[l*9+0]*q1[0]+sK1[l*9+3]*q1[1]+sK1[l*9+6]*q1[2],
                        sK2[l*9+0]*q2[0]+sK2[l*9+3]*q2[1]+sK2[l*9+6]*q2[2]);
            uB1 = pack2(sK1[l*9+1]*q1[0]+sK1[l*9+4]*q1[1]+sK1[l*9+7]*q1[2],
                        sK2[l*9+1]*q2[0]+sK2[l*9+4]*q2[1]+sK2[l*9+7]*q2[2]);
            uB2 = pack2(sK1[l*9+2]*q1[0]+sK1[l*9+5]*q1[1]+sK1[l*9+8]*q1[2],
                        sK2[l*9+2]*q2[0]+sK2[l*9+5]*q2[1]+sK2[l*9+8]*q2[2]);
        }
        __syncthreads();   // the ONLY barrier this layer

        // ---- phase 1: j = 0..t0, BOTH queries (warp-uniform, no masks) ----
        unsigned long long denA=0, aA0=0, aA1=0, aA2=0;
        unsigned long long denB=0, aB0=0, aB1=0, aB2=0;
        const float* rowp = kvb;
        #pragma unroll 1
        for (int j = 0; j <= t0; j++) {
            ulonglong2 r01 = *reinterpret_cast<const ulonglong2*>(rowp);
            unsigned long long hp2 = *reinterpret_cast<const unsigned long long*>(rowp + 4);
            unsigned long long sA, sB;
            MUL2(sA, uA0, r01.x); FMA2(sA, uA1, r01.y, sA); FMA2(sA, uA2, hp2, sA);
            MUL2(sB, uB0, r01.x); FMA2(sB, uB1, r01.y, sB); FMA2(sB, uB2, hp2, sB);
            float a1,a2,b1,b2; unpack2(sA,a1,a2); unpack2(sB,b1,b2);
            unsigned long long eA = pack2(ex2f(a1), ex2f(a2));
            unsigned long long eB = pack2(ex2f(b1), ex2f(b2));
            ADD2(denA, denA, eA);
            FMA2(aA0, eA, r01.x, aA0); FMA2(aA1, eA, r01.y, aA1); FMA2(aA2, eA, hp2, aA2);
            ADD2(denB, denB, eB);
            FMA2(aB0, eB, r01.x, aB0); FMA2(aB1, eB, r01.y, aB1); FMA2(aB2, eB, hp2, aB2);
            rowp += HROW;
        }

        // ---- query A epilogue (frees all A-state before phase 2) ----
        {
            float d1, d2; unpack2(denA, d1, d2);
            float i1 = 1.0f/d1, i2 = 1.0f/d2;
            float h1[3], h2[3];
            unpack2(aA0, h1[0], h2[0]); unpack2(aA1, h1[1], h2[1]); unpack2(aA2, h1[2], h2[2]);
            float o[6];
            #pragma unroll
            for (int d=0; d<3; d++) {
                const float* w1 = &sV1[l*9+d*3];
                const float* w2 = &sV2[l*9+d*3];
                o[d]   = (w1[0]*h1[0]+w1[1]*h1[1]+w1[2]*h1[2]) * i1;
                o[3+d] = (w2[0]*h2[0]+w2[1]*h2[1]+w2[2]*h2[2]) * i2;
            }
            #pragma unroll
            for (int d=0; d<DM; d++) {
                float acc = sX[d][tid];
                const float* ww = &sOW[l*36 + d*DM];
                #pragma unroll
                for (int e=0; e<DM; e++) acc += ww[e]*o[e];
                sX[d][tid] = acc;
            }
        }

        // ---- phase 2: 17 uniform steps, query B only ----
        #pragma unroll 4
        for (int j = 0; j < 17; j++) {
            ulonglong2 r01 = *reinterpret_cast<const ulonglong2*>(rowp);
            unsigned long long hp2 = *reinterpret_cast<const unsigned long long*>(rowp + 4);
            unsigned long long sB;
            MUL2(sB, uB0, r01.x); FMA2(sB, uB1, r01.y, sB); FMA2(sB, uB2, hp2, sB);
            float b1,b2; unpack2(sB,b1,b2);
            unsigned long long eB = pack2(ex2f(b1), ex2f(b2));
            ADD2(denB, denB, eB);
            FMA2(aB0, eB, r01.x, aB0); FMA2(aB1, eB, r01.y, aB1); FMA2(aB2, eB, hp2, aB2);
            rowp += HROW;
        }

        // ---- query B epilogue ----
        {
            float d1, d2; unpack2(denB, d1, d2);
            float i1 = 1.0f/d1, i2 = 1.0f/d2;
            float h1[3], h2[3];
            unpack2(aB0, h1[0], h2[0]); unpack2(aB1, h1[1], h2[1]); unpack2(aB2, h1[2], h2[2]);
            float o[6];
            #pragma unroll
            for (int d=0; d<3; d++) {
                const float* w1 = &sV1[l*9+d*3];
                const float* w2 = &sV2[l*9+d*3];
                o[d]   = (w1[0]*h1[0]+w1[1]*h1[1]+w1[2]*h1[2]) * i1;
                o[3+d] = (w2[0]*h2[0]+w2[1]*h2[1]+w2[2]*h2[2]) * i2;
            }
            #pragma unroll
            for (int d=0; d<DM; d++) {
                float acc = sX[6+d][tid];
                const float* ww = &sOW[l*36 + d*DM];
                #pragma unroll
                for (int e=0; e<DM; e++) acc += ww[e]*o[e];
                sX[6+d][tid] = acc;
            }
        }
        // no trailing barrier: next layer writes the other KV buffer
    }

    // ---- final layernorm + vocab head, both queries ----
    #pragma unroll 1
    for (int qq = 0; qq < 2; qq++) {
        const int xo = qq*DM;
        const int t  = qq ? tB : tA;
        float h[DM];
        {
            float x0=sX[xo+0][tid],x1=sX[xo+1][tid],x2=sX[xo+2][tid],
                  x3=sX[xo+3][tid],x4=sX[xo+4][tid],x5=sX[xo+5][tid];
            float m = (x0+x1+x2+x3+x4+x5) * (1.0f/6.0f);
            h[0]=x0-m; h[1]=x1-m; h[2]=x2-m; h[3]=x3-m; h[4]=x4-m; h[5]=x5-m;
            float v = h[0]*h[0]+h[1]*h[1]+h[2]*h[2]+h[3]*h[3]+h[4]*h[4]+h[5]*h[5];
            float r = rsqrtf(v*(1.0f/6.0f)+1e-5f);
            #pragma unroll
            for (int d=0; d<DM; d++) h[d] = h[d]*r*sLNF[d] + sLNF[DM+d];
        }
        float* op = g_out + (size_t)(b*SEQ + t)*VOC;
        #pragma unroll
        for (int c = 0; c < VOC; c += 2) {
            float l0=0.f, l1=0.f;
            #pragma unroll
            for (int d=0; d<DM; d++) {
                l0 += sHW[c*DM+d]*h[d];
                l1 += sHW[(c+1)*DM+d]*h[d];
            }
            *reinterpret_cast<float2*>(op + c) = make_float2(l0,l1);
        }
    }
}

extern "C" void kernel_launch(void* const* d_in, const int* in_sizes, int n_in,
                              void* d_out, int out_size) {
    const int* idx = (const int*)d_in[0];
    int nb   = in_sizes[0] / SEQ;          // 16384
    int grid = nb / BPB;                   // 512 blocks of 544 threads
    int dyn  = 2*KVBUF*(int)sizeof(float); // 70656 B double-buffered KV
    cudaFuncSetAttribute(addtx_kernel, cudaFuncAttributeMaxDynamicSharedMemorySize, dyn);
    addtx_kernel<<<grid, NTH, dyn>>>(idx,
        (const float*)d_in[1],  (const float*)d_in[2],  (const float*)d_in[3],
        (const float*)d_in[4],  (const float*)d_in[5],  (const float*)d_in[6],
        (const float*)d_in[7],  (const float*)d_in[8],  (const float*)d_in[9],
        (const float*)d_in[10], (const float*)d_in[11], (const float*)d_in[12],
        (const float*)d_in[13], (const float*)d_in[14], (float*)d_out);
}

// round 16
// speedup vs baseline: 1.2991x; 1.2991x over previous
#include <cuda_runtime.h>
#include <cuda_fp16.h>

#define NL   4
#define SEQ  34
#define DM   6
#define VOC  14
#define BPB  16
#define NTH  (SEQ*BPB)            /* 544 = 17 warps exactly */
#define HROW 8                    /* 8 halves = 16B row: 3 half2 h-pairs + pad */
#define KVSTRIDE 280              /* halves; 140 words; bl*140 mod 32 = bl*12 -> conflict-free */
#define KVPAD (BPB*KVSTRIDE + 16) /* overshoot rows 34,35 stay in-bounds (zeroed) */

#define FMA2(d,a,b,c) asm("fma.rn.f32x2 %0, %1, %2, %3;" : "=l"(d) : "l"(a), "l"(b), "l"(c))
#define MUL2(d,a,b)   asm("mul.rn.f32x2 %0, %1, %2;"     : "=l"(d) : "l"(a), "l"(b))
#define ADD2(d,a,b)   asm("add.rn.f32x2 %0, %1, %2;"     : "=l"(d) : "l"(a), "l"(b))

__device__ __forceinline__ unsigned long long pack2(float lo, float hi) {
    unsigned long long r;
    asm("mov.b64 %0, {%1, %2};" : "=l"(r) : "f"(lo), "f"(hi));
    return r;
}
__device__ __forceinline__ void unpack2(unsigned long long v, float& lo, float& hi) {
    asm("mov.b64 {%0, %1}, %2;" : "=f"(lo), "=f"(hi) : "l"(v));
}
__device__ __forceinline__ float ex2f(float x) {
    float r; asm("ex2.approx.f32 %0, %1;" : "=f"(r) : "f"(x)); return r;
}
__device__ __forceinline__ unsigned long long h2_to_f2(unsigned int h2) {
    float2 f = __half22float2(*reinterpret_cast<__half2*>(&h2));
    return pack2(f.x, f.y);
}

__global__ __launch_bounds__(NTH, 2)
void addtx_kernel(const int*   __restrict__ g_idx,
                  const float* __restrict__ g_tok,
                  const float* __restrict__ g_pos,
                  const float* __restrict__ g_lnw,
                  const float* __restrict__ g_lnb,
                  const float* __restrict__ g_q1,
                  const float* __restrict__ g_k1,
                  const float* __restrict__ g_v1,
                  const float* __restrict__ g_q2,
                  const float* __restrict__ g_k2,
                  const float* __restrict__ g_v2,
                  const float* __restrict__ g_ow,
                  const float* __restrict__ g_lnfw,
                  const float* __restrict__ g_lnfb,
                  const float* __restrict__ g_hw,
                  float* __restrict__ g_out)
{
    __shared__ float sQ1[NL*9], sK1[NL*9], sV1[NL*9];
    __shared__ float sQ2[NL*9], sK2[NL*9], sV2[NL*9];
    __shared__ float sOW[NL*36];
    __shared__ float sLNW[NL*DM], sLNB[NL*DM];
    __shared__ float sLNF[2*DM];
    __shared__ float sHW[VOC*DM];
    __shared__ float sTOK[VOC*3];
    __shared__ float sPOS[SEQ*3];
    __shared__ __align__(16) __half sKV[2][KVPAD];   // fp16 rows, double buffer

    const int tid = threadIdx.x;

    for (int i = tid; i < NL*9; i += NTH) {
        sQ1[i]=g_q1[i]; sK1[i]=g_k1[i]; sV1[i]=g_v1[i];
        sQ2[i]=g_q2[i]; sK2[i]=g_k2[i]; sV2[i]=g_v2[i];
    }
    for (int i = tid; i < NL*36; i += NTH) sOW[i]=g_ow[i];
    for (int i = tid; i < NL*DM; i += NTH) { sLNW[i]=g_lnw[i]; sLNB[i]=g_lnb[i]; }
    if (tid < DM) { sLNF[tid]=g_lnfw[tid]; sLNF[DM+tid]=g_lnfb[tid]; }
    for (int i = tid; i < VOC*DM; i += NTH) sHW[i]=g_hw[i];
    for (int i = tid; i < VOC*3; i += NTH) sTOK[i]=g_tok[i];
    for (int i = tid; i < SEQ*3; i += NTH) sPOS[i]=g_pos[i];
    // zero KV (pad rows must be finite: 0*ep stays 0, no NaN poisoning)
    {
        unsigned int* z = reinterpret_cast<unsigned int*>(&sKV[0][0]);
        for (int i = tid; i < 2*KVPAD/2; i += NTH) z[i] = 0u;
    }

    // warps 0..15 -> 8 batches x 4 adjacent t ; warp 16 -> 16 batches x t in {32,33}
    const int w    = tid >> 5;
    const int lane = tid & 31;
    int bl, t, jn;
    if (w < 16) {
        bl = (w & 1) * 8 + (lane & 7);
        t  = ((w >> 1) << 2) + (lane >> 3);
        jn = ((w >> 1) << 2) + 4;        // uniform trip count, multiple of 4
    } else {
        bl = lane & 15;
        t  = 32 + (lane >> 4);
        jn = 36;                          // j=34,35 masked (zeroed pad rows)
    }
    const int b = blockIdx.x * BPB + bl;

    __syncthreads();

    const int tok = g_idx[b*SEQ + t];
    float x[DM];
    #pragma unroll
    for (int d = 0; d < 3; d++) { x[d] = sTOK[tok*3+d]; x[3+d] = sPOS[t*3+d]; }

    const int kvoff = bl*KVSTRIDE;
    const float QS = 0.5773502691896258f * 1.4426950408889634f;  // 1/sqrt(3)*log2(e)
    const unsigned long long NEGINF2 = 0xff800000ff800000ULL;

    #pragma unroll 1
    for (int l = 0; l < NL; l++) {
        __half* kvb = &sKV[l & 1][kvoff];

        // ---- layernorm ----
        float mean = (x[0]+x[1]+x[2]+x[3]+x[4]+x[5]) * (1.0f/6.0f);
        float var = 0.f;
        float h[DM];
        #pragma unroll
        for (int d=0; d<DM; d++) { float dd = x[d]-mean; var += dd*dd; h[d]=dd; }
        float r = rsqrtf(var*(1.0f/6.0f) + 1e-5f);
        #pragma unroll
        for (int d=0; d<DM; d++) h[d] = h[d]*r*sLNW[l*DM+d] + sLNB[l*DM+d];

        // ---- stage h row as fp16 pairs: one STS.128 ----
        {
            __half2 p0 = __floats2half2_rn(h[0], h[3]);
            __half2 p1 = __floats2half2_rn(h[1], h[4]);
            __half2 p2 = __floats2half2_rn(h[2], h[5]);
            uint4 row;
            row.x = *reinterpret_cast<unsigned int*>(&p0);
            row.y = *reinterpret_cast<unsigned int*>(&p1);
            row.z = *reinterpret_cast<unsigned int*>(&p2);
            row.w = 0u;
            *reinterpret_cast<uint4*>(kvb + t*HROW) = row;
        }

        // ---- u = W_k^T (W_q h) per head, log2-domain scaled ----
        float q1[3], q2[3];
        #pragma unroll
        for (int d=0; d<3; d++) {
            const float* ww;
            ww = &sQ1[l*9+d*3]; q1[d] = (ww[0]*h[0]+ww[1]*h[1]+ww[2]*h[2]) * QS;
            ww = &sQ2[l*9+d*3]; q2[d] = (ww[0]*h[3]+ww[1]*h[4]+ww[2]*h[5]) * QS;
        }
        unsigned long long up0, up1, up2;
        up0 = pack2(sK1[l*9+0]*q1[0]+sK1[l*9+3]*q1[1]+sK1[l*9+6]*q1[2],
                    sK2[l*9+0]*q2[0]+sK2[l*9+3]*q2[1]+sK2[l*9+6]*q2[2]);
        up1 = pack2(sK1[l*9+1]*q1[0]+sK1[l*9+4]*q1[1]+sK1[l*9+7]*q1[2],
                    sK2[l*9+1]*q2[0]+sK2[l*9+4]*q2[1]+sK2[l*9+7]*q2[2]);
        up2 = pack2(sK1[l*9+2]*q1[0]+sK1[l*9+5]*q1[1]+sK1[l*9+8]*q1[2],
                    sK2[l*9+2]*q2[0]+sK2[l*9+5]*q2[1]+sK2[l*9+8]*q2[2]);
        __syncthreads();   // the ONLY barrier this layer

        // ---- causal attention: 16B/lane/step (1 LDS.128), unroll-4 ----
        unsigned long long den = 0, a0 = 0, a1 = 0, a2 = 0;
        const __half* rowp = kvb;
        #pragma unroll 1
        for (int j = 0; j < jn; j += 4) {
            #pragma unroll
            for (int u = 0; u < 4; u++) {
                uint4 rv = *reinterpret_cast<const uint4*>(rowp + u*HROW);
                unsigned long long hp0 = h2_to_f2(rv.x);
                unsigned long long hp1 = h2_to_f2(rv.y);
                unsigned long long hp2 = h2_to_f2(rv.z);
                unsigned long long s;
                MUL2(s, up0, hp0);
                FMA2(s, up1, hp1, s);
                FMA2(s, up2, hp2, s);
                s = (j + u <= t) ? s : NEGINF2;   // exp2(-inf)=0
                float s1, s2; unpack2(s, s1, s2);
                unsigned long long ep = pack2(ex2f(s1), ex2f(s2));
                ADD2(den, den, ep);
                FMA2(a0, ep, hp0, a0);
                FMA2(a1, ep, hp1, a1);
                FMA2(a2, ep, hp2, a2);
            }
            rowp += 4*HROW;
        }
        float d1, d2; unpack2(den, d1, d2);
        float i1 = 1.0f/d1, i2 = 1.0f/d2;
        float ah1[3], ah2[3];
        unpack2(a0, ah1[0], ah2[0]);
        unpack2(a1, ah1[1], ah2[1]);
        unpack2(a2, ah1[2], ah2[2]);

        // ---- o = W_v (sum e_j h_j)/den, out projection + residual ----
        float o[6];
        #pragma unroll
        for (int d=0; d<3; d++) {
            const float* w1 = &sV1[l*9+d*3];
            const float* w2 = &sV2[l*9+d*3];
            o[d]   = (w1[0]*ah1[0]+w1[1]*ah1[1]+w1[2]*ah1[2]) * i1;
            o[3+d] = (w2[0]*ah2[0]+w2[1]*ah2[1]+w2[2]*ah2[2]) * i2;
        }
        #pragma unroll
        for (int d=0; d<DM; d++) {
            float acc = x[d];
            const float* ww = &sOW[l*36 + d*DM];
            #pragma unroll
            for (int e=0; e<DM; e++) acc += ww[e]*o[e];
            x[d] = acc;
        }
        // no trailing barrier: next layer writes the other buffer
    }

    // ---- final layernorm + vocab head ----
    {
        float mean = (x[0]+x[1]+x[2]+x[3]+x[4]+x[5]) * (1.0f/6.0f);
        float var = 0.f; float h[DM];
        #pragma unroll
        for (int d=0; d<DM; d++) { float dd=x[d]-mean; var+=dd*dd; h[d]=dd; }
        float r = rsqrtf(var*(1.0f/6.0f)+1e-5f);
        #pragma unroll
        for (int d=0; d<DM; d++) h[d] = h[d]*r*sLNF[d] + sLNF[DM+d];

        float* op = g_out + (size_t)(b*SEQ + t)*VOC;
        #pragma unroll
        for (int c = 0; c < VOC; c += 2) {
            float l0=0.f, l1=0.f;
            #pragma unroll
            for (int d=0; d<DM; d++) {
                l0 += sHW[c*DM+d]*h[d];
                l1 += sHW[(c+1)*DM+d]*h[d];
            }
            *reinterpret_cast<float2*>(op + c) = make_float2(l0,l1);
        }
    }
}

extern "C" void kernel_launch(void* const* d_in, const int* in_sizes, int n_in,
                              void* d_out, int out_size) {
    const int* idx = (const int*)d_in[0];
    int nb   = in_sizes[0] / SEQ;   // 16384
    int grid = nb / BPB;            // 1024 blocks of 544 threads
    addtx_kernel<<<grid, NTH>>>(idx,
        (const float*)d_in[1],  (const float*)d_in[2],  (const float*)d_in[3],
        (const float*)d_in[4],  (const float*)d_in[5],  (const float*)d_in[6],
        (const float*)d_in[7],  (const float*)d_in[8],  (const float*)d_in[9],
        (const float*)d_in[10], (const float*)d_in[11], (const float*)d_in[12],
        (const float*)d_in[13], (const float*)d_in[14], (float*)d_out);
}